// round 9
// baseline (speedup 1.0000x reference)
#include <cuda_runtime.h>
#include <cuda_fp16.h>
#include <mma.h>

using namespace nvcuda;

#define N_NODES 10000
#define N_EDGES 320000
#define ETOT    330000
#define H       128
#define F_IN    256
#define NEG_SLOPE 0.2f

// ---------------- scratch ----------------------------------------------------
__device__ __half g_h16 [N_NODES * H];  // GEMM output, fp16 (gather source)
__device__ __half g_hn16[N_NODES * H];  // post-GAT relu output, fp16 (GEMM2 A)
__device__ __half g_w16 [F_IN * H + H * H];  // fp16 W1 | W2
__device__ float  g_as [N_NODES];
__device__ float  g_ad [N_NODES];
__device__ int    g_cnt[N_NODES];       // invariant: zero at entry of every call
__device__ int    g_off[N_NODES + 1];
__device__ int    g_rank[ETOT];
__device__ int    g_psrc[ETOT];
__device__ float  g_acc2[2];            // invariant: zero at entry of every call
__device__ int    g_done;               // invariant: zero at entry of every call

// ---------------- weight fp32 -> fp16 conversion ------------------------------
__global__ void k_wconv(const float* __restrict__ W1, const float* __restrict__ W2) {
    int i = (blockIdx.x * blockDim.x + threadIdx.x) * 4;
    const int N1 = F_IN * H;
    const int NT = N1 + H * H;
    if (i >= NT) return;
    float4 f = (i < N1) ? *(const float4*)(W1 + i)
                        : *(const float4*)(W2 + (i - N1));
    __half2 h0 = __floats2half2_rn(f.x, f.y);
    __half2 h1 = __floats2half2_rn(f.z, f.w);
    uint2 pk = make_uint2(*(unsigned*)&h0, *(unsigned*)&h1);
    *(uint2*)(g_w16 + i) = pk;
}

// ---------------- histogram + per-edge rank, 4 edges/thread ------------------
__global__ void k_hist(const int* __restrict__ ei) {
    int i = (blockIdx.x * blockDim.x + threadIdx.x) * 4;
    if (i >= ETOT) return;
    if (i < N_EDGES) {
        int4 d4 = *(const int4*)(ei + N_EDGES + i);
        int4 r4;
        r4.x = atomicAdd(&g_cnt[d4.x], 1);
        r4.y = atomicAdd(&g_cnt[d4.y], 1);
        r4.z = atomicAdd(&g_cnt[d4.z], 1);
        r4.w = atomicAdd(&g_cnt[d4.w], 1);
        *(int4*)(g_rank + i) = r4;
    } else {
        int4 r4;
        int d = i - N_EDGES;
        r4.x = atomicAdd(&g_cnt[d + 0], 1);
        r4.y = atomicAdd(&g_cnt[d + 1], 1);
        r4.z = atomicAdd(&g_cnt[d + 2], 1);
        r4.w = atomicAdd(&g_cnt[d + 3], 1);
        *(int4*)(g_rank + i) = r4;
    }
}

// ---------------- scan (warp-shuffle, 1 block x 1024) + g_cnt self-reset -----
__global__ void k_scan() {
    const int CH = 10;
    int t = threadIdx.x;
    int lane = t & 31, wid = t >> 5;
    int base = t * CH;
    int local[CH];
    int sum = 0;
    #pragma unroll
    for (int k = 0; k < CH; k++) {
        int i = base + k;
        int c = (i < N_NODES) ? g_cnt[i] : 0;
        local[k] = sum;
        sum += c;
    }
    int tot = sum;
    int incl = tot;
    #pragma unroll
    for (int o = 1; o < 32; o <<= 1) {
        int v = __shfl_up_sync(0xffffffffu, incl, o);
        if (lane >= o) incl += v;
    }
    __shared__ int wsum[32];
    if (lane == 31) wsum[wid] = incl;
    __syncthreads();
    if (wid == 0) {
        int v = wsum[lane];
        #pragma unroll
        for (int o = 1; o < 32; o <<= 1) {
            int u = __shfl_up_sync(0xffffffffu, v, o);
            if (lane >= o) v += u;
        }
        wsum[lane] = v;
    }
    __syncthreads();
    int excl = incl - tot + (wid > 0 ? wsum[wid - 1] : 0);
    #pragma unroll
    for (int k = 0; k < CH; k++) {
        int i = base + k;
        if (i < N_NODES) {
            g_off[i] = excl + local[k];
            g_cnt[i] = 0;              // restore invariant for next call
        }
    }
    if (t == 0) g_off[N_NODES] = ETOT;
}

__global__ void k_place(const int* __restrict__ ei) {
    int i = (blockIdx.x * blockDim.x + threadIdx.x) * 4;
    if (i >= ETOT) return;
    int4 r4 = *(const int4*)(g_rank + i);
    if (i < N_EDGES) {
        int4 s4 = *(const int4*)(ei + i);
        int4 d4 = *(const int4*)(ei + N_EDGES + i);
        int o0 = g_off[d4.x], o1 = g_off[d4.y], o2 = g_off[d4.z], o3 = g_off[d4.w];
        g_psrc[o0 + r4.x] = s4.x;
        g_psrc[o1 + r4.y] = s4.y;
        g_psrc[o2 + r4.z] = s4.z;
        g_psrc[o3 + r4.w] = s4.w;
    } else {
        int d = i - N_EDGES;
        int o0 = g_off[d + 0], o1 = g_off[d + 1], o2 = g_off[d + 2], o3 = g_off[d + 3];
        g_psrc[o0 + r4.x] = d + 0;
        g_psrc[o1 + r4.y] = d + 1;
        g_psrc[o2 + r4.z] = d + 2;
        g_psrc[o3 + r4.w] = d + 3;
    }
}

// ---------------- wmma GEMM: BM=32, 8 warps, fp16 B, register prefetch -------
// h[M,128] = A[M,K] @ B[K,128] fp16 (fp32 acc).
// Warp w: rows (w>>2)*16, cols (w&3)*32 (2 frags).
#define BM 32
#define BN 128
#define BK 32
#define LDA 40
#define LDB 136
#define LDC 136

__global__ __launch_bounds__(256, 2)
void k_gemm(const float* __restrict__ A32, int wsel,
            const float* __restrict__ att_s, const float* __restrict__ att_d,
            int M, int K) {
    const __half* B16 = g_w16 + (wsel ? F_IN * H : 0);
    __shared__ char smem_raw[BM * LDC * 4];                // 17408 B
    __half* As = (__half*)smem_raw;                        // [BM][LDA]
    __half* Bs = (__half*)(smem_raw + BM * LDA * 2);       // [BK][LDB]
    float*  Cs = (float*)smem_raw;                         // [BM][LDC] (epilogue)

    int tid  = threadIdx.x;
    int warp = tid >> 5;
    int m0   = blockIdx.x * BM;
    int wr   = (warp >> 2) * 16;   // warp row strip (0/16)
    int wc   = (warp & 3) * 32;    // warp col group

    // load mappings
    int ar = tid >> 3, ac = (tid & 7) * 4;    // A: row 0..31, 4-half seg
    int br = tid >> 3, bc = (tid & 7) * 16;   // B: row 0..31, 16-half seg

    wmma::fragment<wmma::accumulator, 16, 16, 16, float> c[2];
    wmma::fill_fragment(c[0], 0.0f);
    wmma::fill_fragment(c[1], 0.0f);

    __half ha[4];
    uint4  hb0, hb1;

    // ---- prologue fetch (k0 = 0)
    {
        int gm = m0 + ar;
        if (gm < M) {
            if (A32) {
                float4 f = *(const float4*)(A32 + (size_t)gm * K + ac);
                ha[0]=__float2half_rn(f.x); ha[1]=__float2half_rn(f.y);
                ha[2]=__float2half_rn(f.z); ha[3]=__float2half_rn(f.w);
            } else {
                *(uint2*)ha = *(const uint2*)(g_hn16 + (size_t)gm * K + ac);
            }
        } else {
            ha[0]=ha[1]=ha[2]=ha[3]=__float2half_rn(0.f);
        }
        const __half* sb = B16 + (size_t)br * BN + bc;
        hb0 = *(const uint4*)sb;
        hb1 = *(const uint4*)(sb + 8);
    }

    for (int k0 = 0; k0 < K; k0 += BK) {
        *(uint2*)(As + ar * LDA + ac) = *(const uint2*)ha;
        *(uint4*)(Bs + br * LDB + bc)     = hb0;
        *(uint4*)(Bs + br * LDB + bc + 8) = hb1;
        __syncthreads();

        int kn = k0 + BK;
        if (kn < K) {
            int gm = m0 + ar;
            if (gm < M) {
                if (A32) {
                    float4 f = *(const float4*)(A32 + (size_t)gm * K + kn + ac);
                    ha[0]=__float2half_rn(f.x); ha[1]=__float2half_rn(f.y);
                    ha[2]=__float2half_rn(f.z); ha[3]=__float2half_rn(f.w);
                } else {
                    *(uint2*)ha = *(const uint2*)(g_hn16 + (size_t)gm * K + kn + ac);
                }
            } else {
                ha[0]=ha[1]=ha[2]=ha[3]=__float2half_rn(0.f);
            }
            const __half* sb = B16 + (size_t)(kn + br) * BN + bc;
            hb0 = *(const uint4*)sb;
            hb1 = *(const uint4*)(sb + 8);
        }

        #pragma unroll
        for (int ks = 0; ks < BK; ks += 16) {
            wmma::fragment<wmma::matrix_a, 16, 16, 16, __half, wmma::row_major> a;
            wmma::load_matrix_sync(a, As + wr * LDA + ks, LDA);
            #pragma unroll
            for (int n = 0; n < 2; n++) {
                wmma::fragment<wmma::matrix_b, 16, 16, 16, __half, wmma::row_major> bfr;
                wmma::load_matrix_sync(bfr, Bs + ks * LDB + wc + n * 16, LDB);
                wmma::mma_sync(c[n], a, bfr, c[n]);
            }
        }
        __syncthreads();
    }

    // ---- epilogue: frags -> smem fp32, fuse att dots + fp16 store
    wmma::store_matrix_sync(Cs + wr * LDC + wc,      c[0], LDC, wmma::mem_row_major);
    wmma::store_matrix_sync(Cs + wr * LDC + wc + 16, c[1], LDC, wmma::mem_row_major);
    __syncthreads();

    {
        int r  = tid >> 3;            // 0..31
        int oc = (tid & 7) * 16;      // 16-col segment
        int gm = m0 + r;
        const float* crow = Cs + r * LDC + oc;
        float ps = 0.f, pd = 0.f;
        __half hv[16];
        #pragma unroll
        for (int q = 0; q < 16; q += 4) {
            float4 f = *(const float4*)(crow + q);
            int col = oc + q;
            ps += f.x * att_s[col]     + f.y * att_s[col + 1]
                + f.z * att_s[col + 2] + f.w * att_s[col + 3];
            pd += f.x * att_d[col]     + f.y * att_d[col + 1]
                + f.z * att_d[col + 2] + f.w * att_d[col + 3];
            hv[q + 0] = __float2half_rn(f.x);
            hv[q + 1] = __float2half_rn(f.y);
            hv[q + 2] = __float2half_rn(f.z);
            hv[q + 3] = __float2half_rn(f.w);
        }
        // reduce across the 8 threads sharing row r (aligned 8-groups in warp)
        ps += __shfl_xor_sync(0xffffffffu, ps, 1);
        pd += __shfl_xor_sync(0xffffffffu, pd, 1);
        ps += __shfl_xor_sync(0xffffffffu, ps, 2);
        pd += __shfl_xor_sync(0xffffffffu, pd, 2);
        ps += __shfl_xor_sync(0xffffffffu, ps, 4);
        pd += __shfl_xor_sync(0xffffffffu, pd, 4);
        if (gm < M) {
            __half* dst = g_h16 + (size_t)gm * H + oc;
            *(uint4*)dst       = *(const uint4*)hv;
            *(uint4*)(dst + 8) = *(const uint4*)(hv + 8);
            if ((tid & 7) == 0) { g_as[gm] = ps; g_ad[gm] = pd; }
        }
    }
}

// ---------------- aggregation: warp per dst node, fp16 gather, unroll 8 ------
__device__ __forceinline__ float lrexp(float e) {
    e = e > 0.f ? e : NEG_SLOPE * e;
    return __expf(e);
}

__device__ __forceinline__ float4 h16_load(int a, int lane) {
    uint2 v = *(const uint2*)(g_h16 + (size_t)a * H + lane * 4);
    float2 f0 = __half22float2(*(const __half2*)&v.x);
    float2 f1 = __half22float2(*(const __half2*)&v.y);
    return make_float4(f0.x, f0.y, f1.x, f1.y);
}

template<bool TAIL>
__global__ void k_agg(const float* __restrict__ bias,
                      const float* __restrict__ Wr, const float* __restrict__ br,
                      const float* __restrict__ Wc, const float* __restrict__ bc,
                      float* __restrict__ out) {
    int warp = threadIdx.x >> 5;
    int lane = threadIdx.x & 31;
    int n = blockIdx.x * 4 + warp;
    __shared__ float s0s[4], s1s[4];

    int s = g_off[n], e = g_off[n + 1];
    float ad = g_ad[n];
    float4 acc = make_float4(0.f, 0.f, 0.f, 0.f);
    float z = 0.f;

    int p = s;
    for (; p + 8 <= e; p += 8) {
        int idx[8];
        #pragma unroll
        for (int q = 0; q < 8; q++) idx[q] = __ldg(&g_psrc[p + q]);
        float w[8];
        #pragma unroll
        for (int q = 0; q < 8; q++) w[q] = lrexp(g_as[idx[q]] + ad);
        float4 hv[8];
        #pragma unroll
        for (int q = 0; q < 8; q++) hv[q] = h16_load(idx[q], lane);
        #pragma unroll
        for (int q = 0; q < 8; q++) {
            z += w[q];
            acc.x += w[q] * hv[q].x;
            acc.y += w[q] * hv[q].y;
            acc.z += w[q] * hv[q].z;
            acc.w += w[q] * hv[q].w;
        }
    }
    for (; p < e; p++) {
        int a0 = __ldg(&g_psrc[p]);
        float w0 = lrexp(g_as[a0] + ad);
        float4 h0 = h16_load(a0, lane);
        z += w0;
        acc.x += w0 * h0.x; acc.y += w0 * h0.y;
        acc.z += w0 * h0.z; acc.w += w0 * h0.w;
    }

    float inv = 1.0f / z;
    float4 b4 = ((const float4*)bias)[lane];
    float4 v;
    v.x = fmaxf(acc.x * inv + b4.x, 0.f);
    v.y = fmaxf(acc.y * inv + b4.y, 0.f);
    v.z = fmaxf(acc.z * inv + b4.z, 0.f);
    v.w = fmaxf(acc.w * inv + b4.w, 0.f);

    if (!TAIL) {
        __half2 hp[2];
        hp[0] = __floats2half2_rn(v.x, v.y);
        hp[1] = __floats2half2_rn(v.z, v.w);
        *(uint2*)(g_hn16 + (size_t)n * H + lane * 4) = *(const uint2*)hp;
    } else {
        float4 wr = ((const float4*)Wr)[lane];
        float dot = v.x * wr.x + v.y * wr.y + v.z * wr.z + v.w * wr.w;
        #pragma unroll
        for (int o = 16; o; o >>= 1) dot += __shfl_down_sync(0xffffffffu, dot, o);
        if (lane == 0) {
            float r = dot + br[0];
            s0s[warp] = r * Wc[n * 2 + 0];
            s1s[warp] = r * Wc[n * 2 + 1];
        }
        __syncthreads();
        if (threadIdx.x == 0) {
            atomicAdd(&g_acc2[0], s0s[0] + s0s[1] + s0s[2] + s0s[3]);
            atomicAdd(&g_acc2[1], s1s[0] + s1s[1] + s1s[2] + s1s[3]);
            __threadfence();
            int old = atomicAdd(&g_done, 1);
            if (old == gridDim.x - 1) {
                g_done = 0;                              // restore invariants
                float r0 = atomicAdd(&g_acc2[0], 0.0f);
                float r1 = atomicAdd(&g_acc2[1], 0.0f);
                g_acc2[0] = 0.0f;
                g_acc2[1] = 0.0f;
                out[0] = r0 + bc[0];
                out[1] = r1 + bc[1];
            }
        }
    }
}

// ---------------- launch -------------------------------------------------------
extern "C" void kernel_launch(void* const* d_in, const int* in_sizes, int n_in,
                              void* d_out, int out_size) {
    const float* x   = (const float*)d_in[0];
    const int*   ei  = (const int*)  d_in[1];
    const float* W1  = (const float*)d_in[2];
    const float* as1 = (const float*)d_in[3];
    const float* ad1 = (const float*)d_in[4];
    const float* b1  = (const float*)d_in[5];
    const float* W2  = (const float*)d_in[6];
    const float* as2 = (const float*)d_in[7];
    const float* ad2 = (const float*)d_in[8];
    const float* b2  = (const float*)d_in[9];
    const float* Wr  = (const float*)d_in[10];
    const float* br  = (const float*)d_in[11];
    const float* Wc  = (const float*)d_in[12];
    const float* bc  = (const float*)d_in[13];
    float* out = (float*)d_out;

    // side stream + events for CSR ∥ GEMM1 overlap (handles created once)
    static cudaStream_t s1 = nullptr;
    static cudaEvent_t ev0 = nullptr, ev1 = nullptr;
    if (s1 == nullptr) {
        cudaStreamCreateWithFlags(&s1, cudaStreamNonBlocking);
        cudaEventCreateWithFlags(&ev0, cudaEventDisableTiming);
        cudaEventCreateWithFlags(&ev1, cudaEventDisableTiming);
    }

    // fork: CSR build on s1
    cudaEventRecord(ev0, 0);
    cudaStreamWaitEvent(s1, ev0, 0);
    k_hist <<<(ETOT / 4 + 255) / 256, 256, 0, s1>>>(ei);
    k_scan <<<1, 1024, 0, s1>>>();
    k_place<<<(ETOT / 4 + 255) / 256, 256, 0, s1>>>(ei);
    cudaEventRecord(ev1, s1);

    int gemm_grid = (N_NODES + BM - 1) / BM;

    // main stream: convert weights, then GEMM1 (concurrent with CSR build)
    k_wconv<<<(F_IN * H + H * H) / (4 * 256), 256>>>(W1, W2);
    k_gemm<<<gemm_grid, 256>>>(x, 0, as1, ad1, N_NODES, F_IN);

    // join
    cudaStreamWaitEvent(0, ev1, 0);

    k_agg<false><<<N_NODES / 4, 128>>>(b1, nullptr, nullptr, nullptr, nullptr, nullptr);

    k_gemm<<<gemm_grid, 256>>>(nullptr, 1, as2, ad2, N_NODES, H);
    k_agg<true><<<N_NODES / 4, 128>>>(b2, Wr, br, Wc, bc, out);
}